// round 2
// baseline (speedup 1.0000x reference)
#include <cuda_runtime.h>

#define CIN 16
#define DIN 64
#define HIN 96
#define WIN 96
#define DD 32
#define HH 48
#define WW 48
#define NVOX (DD*HH*WW)          /* 73728 */
#define RR 3
#define PD (DD+2*RR)             /* 38 */
#define PH (HH+2*RR)             /* 54 */
#define PW (WW+2*RR)             /* 54 */

// Pooled features, channel-grouped layout: index = ((z*H + y)*4 + q)*W + x,
// each element a float4 holding channels 4q..4q+3.
__device__ float4 g_ff[(size_t)DD*HH*4*WW];
__device__ float4 g_fm[(size_t)PD*PH*4*PW];   // zero-padded by RR on each side

// ---------------------------------------------------------------------------
// Pool feat_fix: 2x2x2 mean, write channel-grouped float4 (coalesced).
// ---------------------------------------------------------------------------
__global__ void pool_ff_kernel(const float* __restrict__ in) {
    int i = blockIdx.x * blockDim.x + threadIdx.x;
    if (i >= 4 * NVOX) return;
    int x = i % WW;
    int y = (i / WW) % HH;
    int z = (i / (WW * HH)) % DD;
    int q = i / NVOX;

    float s[4];
#pragma unroll
    for (int cc = 0; cc < 4; cc++) {
        int c = q * 4 + cc;
        const float* p = in + (((size_t)c * DIN + 2 * z) * HIN + 2 * y) * WIN + 2 * x;
        float acc = 0.f;
#pragma unroll
        for (int dz = 0; dz < 2; dz++)
#pragma unroll
            for (int dy = 0; dy < 2; dy++) {
                const float2 v = *(const float2*)(p + (size_t)dz * HIN * WIN + dy * WIN);
                acc += v.x + v.y;
            }
        s[cc] = acc * 0.125f;
    }
    g_ff[((size_t)(z * HH + y) * 4 + q) * WW + x] = make_float4(s[0], s[1], s[2], s[3]);
}

// ---------------------------------------------------------------------------
// Pool feat_mov into zero-padded buffer (pad = RR each side).
// ---------------------------------------------------------------------------
__global__ void pool_fm_kernel(const float* __restrict__ in) {
    int i = blockIdx.x * blockDim.x + threadIdx.x;
    if (i >= 4 * PD * PH * PW) return;
    int x = i % PW;
    int y = (i / PW) % PH;
    int z = (i / (PW * PH)) % PD;
    int q = i / (PD * PH * PW);

    int iz = z - RR, iy = y - RR, ix = x - RR;
    float s[4] = {0.f, 0.f, 0.f, 0.f};
    if (iz >= 0 && iz < DD && iy >= 0 && iy < HH && ix >= 0 && ix < WW) {
#pragma unroll
        for (int cc = 0; cc < 4; cc++) {
            int c = q * 4 + cc;
            const float* p = in + (((size_t)c * DIN + 2 * iz) * HIN + 2 * iy) * WIN + 2 * ix;
            float acc = 0.f;
#pragma unroll
            for (int dz = 0; dz < 2; dz++)
#pragma unroll
                for (int dy = 0; dy < 2; dy++) {
                    const float2 v = *(const float2*)(p + (size_t)dz * HIN * WIN + dy * WIN);
                    acc += v.x + v.y;
                }
            s[cc] = acc * 0.125f;
        }
    }
    g_fm[((size_t)(z * PH + y) * 4 + q) * PW + x] = make_float4(s[0], s[1], s[2], s[3]);
}

// ---------------------------------------------------------------------------
// Top-5 insertion (strict > keeps earliest index on ties, matching lax.top_k)
// ---------------------------------------------------------------------------
#define DEF_TOPK(P)                                                           \
    float P##v0 = -1e30f, P##v1 = -1e30f, P##v2 = -1e30f, P##v3 = -1e30f,     \
          P##v4 = -1e30f;                                                     \
    int P##q0 = 0, P##q1 = 0, P##q2 = 0, P##q3 = 0, P##q4 = 0;

#define TOPK_INS(P, cval, pidx)                                               \
    if (cval > P##v4) {                                                       \
        P##v4 = cval; P##q4 = pidx;                                           \
        if (P##v4 > P##v3) { float t = P##v4; P##v4 = P##v3; P##v3 = t;       \
                             int u = P##q4; P##q4 = P##q3; P##q3 = u; }       \
        if (P##v3 > P##v2) { float t = P##v3; P##v3 = P##v2; P##v2 = t;       \
                             int u = P##q3; P##q3 = P##q2; P##q2 = u; }       \
        if (P##v2 > P##v1) { float t = P##v2; P##v2 = P##v1; P##v1 = t;       \
                             int u = P##q2; P##q2 = P##q1; P##q1 = u; }       \
        if (P##v1 > P##v0) { float t = P##v1; P##v1 = P##v0; P##v0 = t;       \
                             int u = P##q1; P##q1 = P##q0; P##q0 = u; }       \
    }

// dot of 16-ch fixed features (4x float4) with moving features, sequential c
__device__ __forceinline__ float dot16(const float4& a0, const float4& a1,
                                       const float4& a2, const float4& a3,
                                       const float4& m0, const float4& m1,
                                       const float4& m2, const float4& m3) {
    float c = a0.x * m0.x;
    c = fmaf(a0.y, m0.y, c); c = fmaf(a0.z, m0.z, c); c = fmaf(a0.w, m0.w, c);
    c = fmaf(a1.x, m1.x, c); c = fmaf(a1.y, m1.y, c);
    c = fmaf(a1.z, m1.z, c); c = fmaf(a1.w, m1.w, c);
    c = fmaf(a2.x, m2.x, c); c = fmaf(a2.y, m2.y, c);
    c = fmaf(a2.z, m2.z, c); c = fmaf(a2.w, m2.w, c);
    c = fmaf(a3.x, m3.x, c); c = fmaf(a3.y, m3.y, c);
    c = fmaf(a3.z, m3.z, c); c = fmaf(a3.w, m3.w, c);
    return c;
}

// scatter one top-k winner into both output levels
__device__ __forceinline__ void scatter_one(float* __restrict__ out,
                                            int z, int y, int x,
                                            float v, int pj) {
    const float sc[4] = {1.0f, 0.5f, 0.25f, 0.125f};
    int oz = pj / 49 - 3;
    int oy = (pj / 7) % 7 - 3;
    int ox = pj % 7 - 3;

    // level 0: integer displacement, single unit-weight corner
    {
        int tz = min(max(z + oz, 0), DD - 1);
        int ty = min(max(y + oy, 0), HH - 1);
        int tx = min(max(x + ox, 0), WW - 1);
        atomicAdd(&out[(tz * HH + ty) * WW + tx], v);
    }
    // level 1: displacement * 0.5, trilinear splat
    {
        int fz = oz >> 1, fy = oy >> 1, fx = ox >> 1;   // floor(o/2)
        int ez = oz & 1, ey = oy & 1, ex = ox & 1;      // odd -> two corners
        float wv = v * sc[ez + ey + ex];
        float* out1 = out + NVOX;
#pragma unroll
        for (int cz = 0; cz < 2; cz++) {
            if (cz > ez) break;
            int tz = min(max(z + fz + cz, 0), DD - 1);
#pragma unroll
            for (int cy = 0; cy < 2; cy++) {
                if (cy > ey) break;
                int ty = min(max(y + fy + cy, 0), HH - 1);
#pragma unroll
                for (int cx = 0; cx < 2; cx++) {
                    if (cx > ex) break;
                    int tx = min(max(x + fx + cx, 0), WW - 1);
                    atomicAdd(&out1[(tz * HH + ty) * WW + tx], wv);
                }
            }
        }
    }
}

// ---------------------------------------------------------------------------
// Correlation + top-5 + scatter. One thread handles TWO z-adjacent voxels
// (z, z+1): their 7-slice fm windows overlap in 6 slices, so each loaded m
// vector feeds both dot products (1.75x fewer loads, 2x FMA per load).
// ---------------------------------------------------------------------------
__global__ void __launch_bounds__(128) corr_scatter_kernel(float* __restrict__ out) {
    int n = blockIdx.x * blockDim.x + threadIdx.x;
    if (n >= NVOX / 2) return;
    int x = n % WW;
    int y = (n / WW) % HH;
    int z = (n / (WW * HH)) * 2;

    const float4* fa = &g_ff[((size_t)(z * HH + y) * 4) * WW + x];
    float4 a0 = fa[0], a1 = fa[WW], a2 = fa[2 * WW], a3 = fa[3 * WW];
    const float4* fb = &g_ff[((size_t)((z + 1) * HH + y) * 4) * WW + x];
    float4 b0 = fb[0], b1 = fb[WW], b2 = fb[2 * WW], b3 = fb[3 * WW];

    DEF_TOPK(A)
    DEF_TOPK(B)

    for (int pza = 0; pza < 8; pza++) {          // absolute slice: fm[z+pza-3]
        const bool doA = (pza < 7);              // output z   uses pz = pza
        const bool doB = (pza >= 1);             // output z+1 uses pz = pza-1
        const int baseA = pza * 49;
        const int baseB = (pza - 1) * 49;
        for (int py = 0; py < 7; py++) {
            const float4* mb =
                &g_fm[((size_t)((z + pza) * PH + (y + py)) * 4) * PW + x];
            const int rowA = baseA + py * 7;
            const int rowB = baseB + py * 7;
#pragma unroll
            for (int px = 0; px < 7; px++) {
                float4 m0 = mb[px];
                float4 m1 = mb[PW + px];
                float4 m2 = mb[2 * PW + px];
                float4 m3 = mb[3 * PW + px];
                if (doA) {
                    float c = dot16(a0, a1, a2, a3, m0, m1, m2, m3);
                    TOPK_INS(A, c, rowA + px)
                }
                if (doB) {
                    float c = dot16(b0, b1, b2, b3, m0, m1, m2, m3);
                    TOPK_INS(B, c, rowB + px)
                }
            }
        }
    }

    float av[5] = {Av0, Av1, Av2, Av3, Av4};
    int aq[5] = {Aq0, Aq1, Aq2, Aq3, Aq4};
    float bv[5] = {Bv0, Bv1, Bv2, Bv3, Bv4};
    int bq[5] = {Bq0, Bq1, Bq2, Bq3, Bq4};
#pragma unroll
    for (int j = 0; j < 5; j++) scatter_one(out, z, y, x, av[j], aq[j]);
#pragma unroll
    for (int j = 0; j < 5; j++) scatter_one(out, z + 1, y, x, bv[j], bq[j]);
}

// ---------------------------------------------------------------------------
extern "C" void kernel_launch(void* const* d_in, const int* in_sizes, int n_in,
                              void* d_out, int out_size) {
    (void)in_sizes; (void)n_in;
    const float* feat_fix = (const float*)d_in[0];
    const float* feat_mov = (const float*)d_in[1];
    float* out = (float*)d_out;

    cudaMemsetAsync(out, 0, (size_t)out_size * sizeof(float), 0);

    int t = 256;
    pool_ff_kernel<<<(4 * NVOX + t - 1) / t, t>>>(feat_fix);
    pool_fm_kernel<<<(4 * PD * PH * PW + t - 1) / t, t>>>(feat_mov);
    corr_scatter_kernel<<<(NVOX / 2 + 127) / 128, 128>>>(out);
}